// round 14
// baseline (speedup 1.0000x reference)
#include <cuda_runtime.h>
#include <cuda_fp16.h>
#include <stdint.h>
#include <math.h>

#define BB 8
#define CC 64
#define HH 256
#define WW 256
#define OHH 131
#define OWW 131
#define PP (OHH*OWW)      /* 17161 */
#define PSTRH 17168       /* fp16 channel stride (16B rows) */
#define HWSZ (HH*WW)

// db4 filters
__constant__ float DEC_LO[8] = {
    -0.010597401784997278f, 0.032883011666982945f, 0.030841381835986965f,
    -0.18703481171888114f, -0.02798376941698385f, 0.6308807679295904f,
    0.7148465705525415f, 0.23037781330885523f };
__constant__ float DEC_HI[8] = {
    -0.23037781330885523f, 0.7148465705525415f, -0.6308807679295904f,
    -0.02798376941698385f, 0.18703481171888114f, 0.030841381835986965f,
    -0.032883011666982945f, -0.010597401784997278f };

// Scratch
__device__ __align__(16) __half g_ffh[(size_t)BB*256*PSTRH + 8192];
__device__ __align__(16) __half g_zh[(size_t)BB*128*PSTRH + 8192];
__device__ __align__(16) __half g_reconh[(size_t)BB*64*HWSZ];
__device__ __align__(16) __half g_w1h[128*256];
__device__ __align__(16) __half g_w2h[256*128];
__device__ __align__(16) __half g_wfh[64*128];
__device__ float g_stats[128];
__device__ float g_density[512];

// ---- helpers ----
__device__ __forceinline__ void mma_f16(float4& d, const uint32_t a[4], uint32_t b0, uint32_t b1) {
    asm volatile("mma.sync.aligned.m16n8k16.row.col.f32.f16.f16.f32 "
        "{%0,%1,%2,%3}, {%4,%5,%6,%7}, {%8,%9}, {%0,%1,%2,%3};"
        : "+f"(d.x), "+f"(d.y), "+f"(d.z), "+f"(d.w)
        : "r"(a[0]), "r"(a[1]), "r"(a[2]), "r"(a[3]), "r"(b0), "r"(b1));
}
__device__ __forceinline__ void ldsm4(uint32_t r[4], uint32_t a) {
    asm volatile("ldmatrix.sync.aligned.m8n8.x4.shared.b16 {%0,%1,%2,%3}, [%4];"
        : "=r"(r[0]), "=r"(r[1]), "=r"(r[2]), "=r"(r[3]) : "r"(a));
}
__device__ __forceinline__ void ldsm4t(uint32_t r[4], uint32_t a) {
    asm volatile("ldmatrix.sync.aligned.m8n8.x4.trans.shared.b16 {%0,%1,%2,%3}, [%4];"
        : "=r"(r[0]), "=r"(r[1]), "=r"(r[2]), "=r"(r[3]) : "r"(a));
}
__device__ __forceinline__ uint32_t packh2(float a, float b) {
    __half2 h = __floats2half2_rn(a, b);
    return *(uint32_t*)&h;
}
// packed f32x2
__device__ __forceinline__ uint64_t pk2(float lo, float hi) {
    uint64_t r; asm("mov.b64 %0, {%1,%2};" : "=l"(r) : "f"(lo), "f"(hi)); return r;
}
__device__ __forceinline__ void upk2(uint64_t v, float& lo, float& hi) {
    asm("mov.b64 {%0,%1}, %2;" : "=f"(lo), "=f"(hi) : "l"(v));
}
__device__ __forceinline__ uint64_t fma2(uint64_t a, uint64_t b, uint64_t c) {
    uint64_t d; asm("fma.rn.f32x2 %0, %1, %2, %3;" : "=l"(d) : "l"(a), "l"(b), "l"(c)); return d;
}

// ---------------- K0: prep ----------------
__global__ void k_prep(const float* __restrict__ w1, const float* __restrict__ w2,
                       const float* __restrict__ wf) {
    int i = blockIdx.x * 256 + threadIdx.x;     // 32768
    g_w1h[i] = __float2half(w1[i]);
    g_w2h[i] = __float2half(w2[i]);
    if (i < 8192) g_wfh[i] = __float2half(wf[i]);
    if (i < 512) g_density[i] = 0.f;
    if (i < 128) g_stats[i] = 0.f;
}

// ---------------- K2: DWT2 -> g_ffh + inline density (f32x2 math) ----------------
__global__ void __launch_bounds__(256) k_dwt(const float* __restrict__ x) {
    const int gi0 = blockIdx.x * 8;
    const int bc = blockIdx.y;
    __shared__ float sIn[22][272];
    __shared__ float sT[2][22][132];
    const float* xp = x + (size_t)bc * HWSZ;

    int cnt = 0;
    const bool owner = (blockIdx.x < 16);
    for (int idx = threadIdx.x; idx < 22 * 64; idx += 256) {
        int r = idx >> 6, q = idx & 63;
        int m = 2 * gi0 - 6 + r;
        m = (m < 0) ? (-1 - m) : ((m > 255) ? (511 - m) : m);
        float4 v = *(const float4*)&xp[m * 256 + 4 * q];
        *(float4*)&sIn[r][8 + 4 * q] = v;
        if (owner && r >= 6)
            cnt += (v.x != 0.f) + (v.y != 0.f) + (v.z != 0.f) + (v.w != 0.f);
    }
    if (owner) {
        #pragma unroll
        for (int off = 16; off > 0; off >>= 1)
            cnt += __shfl_down_sync(0xffffffffu, cnt, off);
        if ((threadIdx.x & 31) == 0 && cnt > 0)
            atomicAdd(&g_density[bc], (float)cnt);
    }
    for (int idx = threadIdx.x; idx < 22 * 12; idx += 256) {
        int r = idx / 12, e = idx % 12;
        int m = 2 * gi0 - 6 + r;
        m = (m < 0) ? (-1 - m) : ((m > 255) ? (511 - m) : m);
        int col = (e < 6) ? (2 + e) : (258 + e);
        int n = (e < 6) ? (5 - e) : (261 - e);
        sIn[r][col] = xp[m * 256 + n];
    }
    uint64_t cpk[8];
    #pragma unroll
    for (int v = 0; v < 8; v++) cpk[v] = pk2(DEC_LO[7 - v], DEC_HI[7 - v]);
    const uint64_t z2 = pk2(0.f, 0.f);
    __syncthreads();
    for (int idx = threadIdx.x; idx < 22 * 131; idx += 256) {
        int r = idx / 131, j = idx % 131;
        uint64_t acc = z2;
        #pragma unroll
        for (int v = 0; v < 8; v++) {
            float xv = sIn[r][2 * j + v + 2];
            acc = fma2(pk2(xv, xv), cpk[v], acc);
        }
        float lo, hi; upk2(acc, lo, hi);
        sT[0][r][j] = lo; sT[1][r][j] = hi;
    }
    __syncthreads();
    int b = bc >> 6, c = bc & 63;
    __half* base = g_ffh + ((size_t)b * 256 + c) * PSTRH;
    for (int idx = threadIdx.x; idx < 8 * 131; idx += 256) {
        int ii = idx / 131, j = idx % 131;
        int gi = gi0 + ii;
        if (gi < OHH) {
            uint64_t accA = z2, accB = z2;
            #pragma unroll
            for (int u = 0; u < 8; u++) {
                float tl = sT[0][2 * ii + u][j], th = sT[1][2 * ii + u][j];
                accA = fma2(pk2(tl, tl), cpk[u], accA);
                accB = fma2(pk2(th, th), cpk[u], accB);
            }
            float aa, da, ad, dd;
            upk2(accA, aa, da); upk2(accB, ad, dd);
            int p = gi * OWW + j;
            base[p] = __float2half(aa);
            base[(size_t)64 * PSTRH + p] = __float2half(da);
            base[(size_t)128 * PSTRH + p] = __float2half(ad);
            base[(size_t)192 * PSTRH + p] = __float2half(dd);
        }
    }
}

// ---------------- K3: gemm1 (fp16 mma + ldmatrix, cp.async 4-stage), z -> fp16 ----------------
#define G1_SAH 2176
#define G1_SWH 3072

__global__ void __launch_bounds__(256) k_gemm1(const float* __restrict__ b1) {
    __shared__ __half sA[4][16][136];
    __shared__ __half sW[4][128][24];
    const int b = blockIdx.y;
    const int p0 = blockIdx.x * 128;
    const int tid = threadIdx.x;
    const __half* ffb = g_ffh + (size_t)b * 256 * PSTRH;
    uint32_t saddrA = (uint32_t)__cvta_generic_to_shared(&sA[0][0][0]);
    uint32_t saddrW = (uint32_t)__cvta_generic_to_shared(&sW[0][0][0]);

    const int ar_ = tid >> 4, ac8 = (tid & 15) * 8;
    const int wo_ = tid >> 1, wk8 = (tid & 1) * 8;

    #define G1_ISSUE(stage, qc) do { \
        const __half* srcA = ffb + (size_t)((qc) + ar_) * PSTRH + p0 + ac8; \
        uint32_t dstA = saddrA + (uint32_t)(((stage) * G1_SAH + ar_ * 136 + ac8) * 2); \
        int rem = PP - (p0 + ac8); \
        int bytes = (rem >= 8) ? 16 : ((rem > 0) ? rem * 2 : 0); \
        asm volatile("cp.async.ca.shared.global [%0], [%1], 16, %2;" \
                     :: "r"(dstA), "l"(srcA), "r"(bytes)); \
        const __half* srcW = g_w1h + wo_ * 256 + (qc) + wk8; \
        uint32_t dstW = saddrW + (uint32_t)(((stage) * G1_SWH + wo_ * 24 + wk8) * 2); \
        asm volatile("cp.async.ca.shared.global [%0], [%1], 16;" \
                     :: "r"(dstW), "l"(srcW)); \
    } while (0)

    G1_ISSUE(0, 0);   asm volatile("cp.async.commit_group;" ::: "memory");
    G1_ISSUE(1, 16);  asm volatile("cp.async.commit_group;" ::: "memory");
    G1_ISSUE(2, 32);  asm volatile("cp.async.commit_group;" ::: "memory");

    const int w = tid >> 5, lane = tid & 31;
    const int gid = lane >> 2, tig = lane & 3;
    const int obase = (w >> 1) * 32, pbase = (w & 1) * 64;
    const int q = lane >> 3, r = lane & 7;
    const uint32_t aoff = (uint32_t)((((q & 1) * 8 + r) * 136 + (q >> 1) * 8) * 2);
    const uint32_t woff0 = (uint32_t)(((obase + (q & 1) * 8 + r) * 24 + (q >> 1) * 8) * 2);
    const uint32_t woff1 = woff0 + 16 * 24 * 2;
    float4 acc[2][8] = {};
    const bool fullA = (p0 + 128 <= PP);

    for (int i = 0; i < 16; i++) {
        asm volatile("cp.async.wait_group 2;" ::: "memory");
        __syncthreads();
        if (i + 3 < 16) { G1_ISSUE((i + 3) & 3, (i + 3) * 16); }
        asm volatile("cp.async.commit_group;" ::: "memory");
        uint32_t baA = saddrA + (uint32_t)((i & 3) * G1_SAH * 2);
        uint32_t baW = saddrW + (uint32_t)((i & 3) * G1_SWH * 2);
        uint32_t wa0[4], wa1[4];
        ldsm4(wa0, baW + woff0);
        ldsm4(wa1, baW + woff1);
        #pragma unroll
        for (int j = 0; j < 4; j++) {
            uint32_t ab[4];
            ldsm4t(ab, baA + aoff + (uint32_t)((pbase + j * 16) * 2));
            mma_f16(acc[0][2 * j],     wa0, ab[0], ab[1]);
            mma_f16(acc[1][2 * j],     wa1, ab[0], ab[1]);
            mma_f16(acc[0][2 * j + 1], wa0, ab[2], ab[3]);
            mma_f16(acc[1][2 * j + 1], wa1, ab[2], ab[3]);
        }
    }
    float s1[2] = {0.f, 0.f}, s2[2] = {0.f, 0.f};
    __half* zb = g_zh + (size_t)b * 128 * PSTRH;
    #pragma unroll
    for (int mt = 0; mt < 2; mt++) {
        int o1 = obase + mt * 16 + gid;
        float bia = b1[o1], bib = b1[o1 + 8];
        #pragma unroll
        for (int nt = 0; nt < 8; nt++) {
            int p = p0 + pbase + nt * 8 + 2 * tig;
            float vx = acc[mt][nt].x + bia, vy = acc[mt][nt].y + bia;
            float vz = acc[mt][nt].z + bib, vw = acc[mt][nt].w + bib;
            if (fullA) {
                s1[mt] += vx + vy + vz + vw;
                s2[mt] += vx*vx + vy*vy + vz*vz + vw*vw;
                *(__half2*)&zb[(size_t)o1 * PSTRH + p] = __floats2half2_rn(vx, vy);
                *(__half2*)&zb[(size_t)(o1 + 8) * PSTRH + p] = __floats2half2_rn(vz, vw);
            } else {
                if (p < PP)     { zb[(size_t)o1*PSTRH + p] = __float2half_rn(vx);     zb[(size_t)(o1+8)*PSTRH + p] = __float2half_rn(vz);     s1[mt] += vx + vz; s2[mt] += vx*vx + vz*vz; }
                if (p + 1 < PP) { zb[(size_t)o1*PSTRH + p + 1] = __float2half_rn(vy); zb[(size_t)(o1+8)*PSTRH + p + 1] = __float2half_rn(vw); s1[mt] += vy + vw; s2[mt] += vy*vy + vw*vw; }
            }
        }
    }
    #pragma unroll
    for (int off = 16; off > 0; off >>= 1) {
        s1[0] += __shfl_down_sync(0xffffffffu, s1[0], off);
        s2[0] += __shfl_down_sync(0xffffffffu, s2[0], off);
        s1[1] += __shfl_down_sync(0xffffffffu, s1[1], off);
        s2[1] += __shfl_down_sync(0xffffffffu, s2[1], off);
    }
    if (lane == 0) {
        int g0 = (w >> 1) * 2;
        atomicAdd(&g_stats[(b * 8 + g0) * 2],     s1[0]);
        atomicAdd(&g_stats[(b * 8 + g0) * 2 + 1], s2[0]);
        atomicAdd(&g_stats[(b * 8 + g0 + 1) * 2],     s1[1]);
        atomicAdd(&g_stats[(b * 8 + g0 + 1) * 2 + 1], s2[1]);
    }
}

// ---------------- K5: gemm2 single-pass: gated = (gelu(GN(z)) @ w2^T + b2) * gate ----------------
// M=256 outs, N=64 px per block. W: cp.async 3-stage. A: register-prefetch + fused GN/GELU.
#define G2_SWH 6144   /* 256*24 halfs per stage */

__global__ void __launch_bounds__(256) k_gemm2(const float* __restrict__ b2,
                                               const float* __restrict__ gamma,
                                               const float* __restrict__ beta,
                                               const float* __restrict__ g1,
                                               const float* __restrict__ gb1,
                                               const float* __restrict__ g2,
                                               const float* __restrict__ gb2) {
    __shared__ __half sW[3][256][24];
    __shared__ __half sA[2][16][72];
    __shared__ float sScale[128], sShift[128];
    __shared__ float sH[16], sGates[4];
    const int b = blockIdx.y;
    const int p0 = blockIdx.x * 64;
    const int tid = threadIdx.x;
    const int w = tid >> 5, lane = tid & 31;
    const __half* zb = g_zh + (size_t)b * 128 * PSTRH;
    uint32_t saddrA = (uint32_t)__cvta_generic_to_shared(&sA[0][0][0]);
    uint32_t saddrW = (uint32_t)__cvta_generic_to_shared(&sW[0][0][0]);

    // W issue: thread tid covers w2 row (256 rows), 16 halfs per k-chunk
    #define G2_WISSUE(stage, qc) do { \
        const __half* srcW = g_w2h + tid * 128 + (qc); \
        uint32_t dstW = saddrW + (uint32_t)(((stage) * G2_SWH + tid * 24) * 2); \
        asm volatile("cp.async.ca.shared.global [%0], [%1], 16;" :: "r"(dstW), "l"(srcW)); \
        asm volatile("cp.async.ca.shared.global [%0], [%1], 16;" :: "r"(dstW + 16), "l"(srcW + 8)); \
    } while (0)

    G2_WISSUE(0, 0);  asm volatile("cp.async.commit_group;" ::: "memory");
    G2_WISSUE(1, 16); asm volatile("cp.async.commit_group;" ::: "memory");

    // prologue: GN scale/shift + gates (overlaps cp.async)
    if (tid < 128) {
        int g = tid >> 4;
        float s1 = g_stats[(b * 8 + g) * 2], s2 = g_stats[(b * 8 + g) * 2 + 1];
        float invN = 1.f / (16.f * (float)PP);
        float mu = s1 * invN;
        float rs = rsqrtf(s2 * invN - mu * mu + 1e-5f);
        float sc = rs * gamma[tid];
        sScale[tid] = sc;
        sShift[tid] = beta[tid] - mu * sc;
    }
    if (w == 4) {
        const float invHW = 1.f / (float)HWSZ;
        if (lane < 16) {
            float s = gb1[lane];
            #pragma unroll 4
            for (int c = 0; c < 64; c++) s += (g_density[b * 64 + c] * invHW) * g1[lane * 64 + c];
            sH[lane] = fmaxf(s, 0.f);
        }
        __syncwarp();
        if (lane < 4) {
            float s = gb2[lane];
            #pragma unroll
            for (int i = 0; i < 16; i++) s += sH[i] * g2[lane * 16 + i];
            sGates[lane] = 1.f / (1.f + expf(-s));
        }
    }
    __syncthreads();   // sScale/sShift visible for A processing

    const int ar = tid >> 4, ac = (tid & 15) * 4;   // A: 16 k-rows x 64 px, 4 els/thread
    uint2 rawA;
    #define G2_ALOAD(qc) do { rawA = *(const uint2*)&zb[(size_t)((qc) + ar) * PSTRH + p0 + ac]; } while (0)
    #define G2_APROC(st, qc) do { \
        float2 f0 = __half22float2(*(__half2*)&rawA.x); \
        float2 f1 = __half22float2(*(__half2*)&rawA.y); \
        float sc_ = sScale[(qc) + ar], sh_ = sShift[(qc) + ar]; \
        f0.x = f0.x * sc_ + sh_; f0.x = 0.5f * f0.x * (1.f + erff(f0.x * 0.70710678118654752f)); \
        f0.y = f0.y * sc_ + sh_; f0.y = 0.5f * f0.y * (1.f + erff(f0.y * 0.70710678118654752f)); \
        f1.x = f1.x * sc_ + sh_; f1.x = 0.5f * f1.x * (1.f + erff(f1.x * 0.70710678118654752f)); \
        f1.y = f1.y * sc_ + sh_; f1.y = 0.5f * f1.y * (1.f + erff(f1.y * 0.70710678118654752f)); \
        uint2 pk; pk.x = packh2(f0.x, f0.y); pk.y = packh2(f1.x, f1.y); \
        *(uint2*)&sA[st][ar][ac] = pk; \
    } while (0)

    G2_ALOAD(0); G2_APROC(0, 0);     // A(0) ready in sA[0]
    G2_ALOAD(16);                    // raw A(1) in flight
    __syncthreads();

    const int gid = lane >> 2, tig = lane & 3;
    const int obase = (w >> 1) * 64, pbase = (w & 1) * 32;
    const int q = lane >> 3, r = lane & 7;
    const uint32_t aoff = (uint32_t)((((q & 1) * 8 + r) * 72 + (q >> 1) * 8) * 2);
    uint32_t woff[4];
    #pragma unroll
    for (int mt = 0; mt < 4; mt++)
        woff[mt] = (uint32_t)(((obase + mt * 16 + (q & 1) * 8 + r) * 24 + (q >> 1) * 8) * 2);
    float4 acc[4][4] = {};
    const bool fullA = (p0 + 64 <= PP);

    for (int i = 0; i < 8; i++) {
        asm volatile("cp.async.wait_group 1;" ::: "memory");
        __syncthreads();                       // W(i) ready; sA[(i)&1] stores visible
        if (i + 2 < 8) { G2_WISSUE((i + 2) % 3, (i + 2) * 16); }
        asm volatile("cp.async.commit_group;" ::: "memory");
        if (i + 1 < 8) {
            G2_APROC((i + 1) & 1, (i + 1) * 16);   // GELU raw(i+1), store
            if (i + 2 < 8) G2_ALOAD((i + 2) * 16); // issue raw(i+2)
        }
        uint32_t baA = saddrA + (uint32_t)((i & 1) * 16 * 72 * 2);
        uint32_t baW = saddrW + (uint32_t)((i % 3) * G2_SWH * 2);
        uint32_t wa[4][4];
        #pragma unroll
        for (int mt = 0; mt < 4; mt++) ldsm4(wa[mt], baW + woff[mt]);
        #pragma unroll
        for (int j = 0; j < 2; j++) {
            uint32_t ab[4];
            ldsm4t(ab, baA + aoff + (uint32_t)((pbase + j * 16) * 2));
            #pragma unroll
            for (int mt = 0; mt < 4; mt++) {
                mma_f16(acc[mt][2 * j],     wa[mt], ab[0], ab[1]);
                mma_f16(acc[mt][2 * j + 1], wa[mt], ab[2], ab[3]);
            }
        }
    }
    __half* gbuf = g_ffh + (size_t)b * 256 * PSTRH;
    #pragma unroll
    for (int mt = 0; mt < 4; mt++) {
        int o1 = obase + mt * 16 + gid;
        float ga = sGates[o1 >> 6];
        float gb_ = sGates[(o1 + 8) >> 6];
        float bia = b2[o1], bib = b2[o1 + 8];
        #pragma unroll
        for (int nt = 0; nt < 4; nt++) {
            int p = p0 + pbase + nt * 8 + 2 * tig;
            float vx = (acc[mt][nt].x + bia) * ga, vy = (acc[mt][nt].y + bia) * ga;
            float vz = (acc[mt][nt].z + bib) * gb_, vw = (acc[mt][nt].w + bib) * gb_;
            if (fullA) {
                *(__half2*)&gbuf[(size_t)o1 * PSTRH + p] = __floats2half2_rn(vx, vy);
                *(__half2*)&gbuf[(size_t)(o1 + 8) * PSTRH + p] = __floats2half2_rn(vz, vw);
            } else {
                if (p < PP)     { gbuf[(size_t)o1*PSTRH + p] = __float2half_rn(vx);     gbuf[(size_t)(o1+8)*PSTRH + p] = __float2half_rn(vz); }
                if (p + 1 < PP) { gbuf[(size_t)o1*PSTRH + p + 1] = __float2half_rn(vy); gbuf[(size_t)(o1+8)*PSTRH + p + 1] = __float2half_rn(vw); }
            }
        }
    }
}

// ---------------- K6: IDWT2 -> g_reconh (f32x2 math) ----------------
__global__ void __launch_bounds__(256) k_idwt() {
    int tile = blockIdx.x;
    int bc = blockIdx.y;
    int h0 = (tile >> 2) * 32;
    int w0 = (tile & 3) * 64;
    int b = bc >> 6, c = bc & 63;
    __shared__ float scoef[4][19][36];
    __shared__ float stmp[4][19][68];
    const __half* gb = g_ffh + ((size_t)b * 256 + c) * PSTRH;
    int ib0 = h0 >> 1, jb0 = w0 >> 1;

    for (int idx = threadIdx.x; idx < 4 * 19 * 35; idx += 256) {
        int k = idx / (19 * 35); int rem = idx % (19 * 35);
        int il = rem / 35, jl = rem % 35;
        scoef[k][il][jl] = __half2float(gb[(size_t)k * 64 * PSTRH + (ib0 + il) * OWW + jb0 + jl]);
    }
    uint64_t qlo[4], qhi[4];
    #pragma unroll
    for (int t = 0; t < 4; t++) {
        qlo[t] = pk2(DEC_LO[2 * t + 1], DEC_LO[2 * t]);
        qhi[t] = pk2(DEC_HI[2 * t + 1], DEC_HI[2 * t]);
    }
    const uint64_t z2 = pk2(0.f, 0.f);
    __syncthreads();
    for (int s = threadIdx.x; s < 19 * 16; s += 256) {
        int il = s >> 4, ws = s & 15;
        int wl = ws * 4, jb = wl >> 1;
        #pragma unroll
        for (int k = 0; k < 4; k++) {
            const uint64_t* qq = (k < 2) ? qlo : qhi;
            float c0 = scoef[k][il][jb],     c1 = scoef[k][il][jb + 1];
            float c2 = scoef[k][il][jb + 2], c3 = scoef[k][il][jb + 3];
            float c4 = scoef[k][il][jb + 4];
            uint64_t o01 = z2, o23 = z2;
            o01 = fma2(pk2(c0, c0), qq[0], o01);
            o01 = fma2(pk2(c1, c1), qq[1], o01);
            o01 = fma2(pk2(c2, c2), qq[2], o01);
            o01 = fma2(pk2(c3, c3), qq[3], o01);
            o23 = fma2(pk2(c1, c1), qq[0], o23);
            o23 = fma2(pk2(c2, c2), qq[1], o23);
            o23 = fma2(pk2(c3, c3), qq[2], o23);
            o23 = fma2(pk2(c4, c4), qq[3], o23);
            float a0, a1, a2, a3;
            upk2(o01, a0, a1); upk2(o23, a2, a3);
            stmp[k][il][wl + 0] = a0;
            stmp[k][il][wl + 1] = a1;
            stmp[k][il][wl + 2] = a2;
            stmp[k][il][wl + 3] = a3;
        }
    }
    __syncthreads();
    __half* rb = g_reconh + ((size_t)b * 64 + c) * HWSZ;
    for (int s = threadIdx.x; s < 512; s += 256) {
        int wlh = s & 63, hs = s >> 6;
        int hb = hs * 4, ib = hb >> 1;
        uint64_t acc01 = z2, acc23 = z2;
        #pragma unroll
        for (int k = 0; k < 4; k++) {
            const uint64_t* rr = (k & 1) ? qhi : qlo;
            uint64_t tp[5];
            #pragma unroll
            for (int m = 0; m < 5; m++) {
                float tv = stmp[k][ib + m][wlh];
                tp[m] = pk2(tv, tv);
            }
            #pragma unroll
            for (int m = 0; m < 4; m++) {
                acc01 = fma2(tp[m],     rr[m], acc01);
                acc23 = fma2(tp[m + 1], rr[m], acc23);
            }
        }
        float a0, a1, a2, a3;
        upk2(acc01, a0, a1); upk2(acc23, a2, a3);
        rb[(h0 + hb + 0) * WW + w0 + wlh] = __float2half(a0);
        rb[(h0 + hb + 1) * WW + w0 + wlh] = __float2half(a1);
        rb[(h0 + hb + 2) * WW + w0 + wlh] = __float2half(a2);
        rb[(h0 + hb + 3) * WW + w0 + wlh] = __float2half(a3);
    }
}

// ---------------- K7: fused = [x, recon] @ wf^T + bf (fp16 mma) ----------------
__global__ void __launch_bounds__(256) k_final(const float* __restrict__ x,
                                               const float* __restrict__ bf,
                                               float* __restrict__ out) {
    const int b = blockIdx.y;
    const int p0 = blockIdx.x * 256;
    __shared__ __half sW[2][64][24];
    __shared__ __half sA[2][16][264];
    const int tid = threadIdx.x;
    const int w = tid >> 5, lane = tid & 31;
    const int gid = lane >> 2, tig = lane & 3;
    const int obase = (w >> 2) * 32, pbase = (w & 3) * 64;
    float4 acc[2][8] = {};
    const float* xb = x + (size_t)b * 64 * HWSZ;
    const __half* rbh = g_reconh + (size_t)b * 64 * HWSZ;

    const int row0 = tid >> 5, cb0 = (tid & 31) * 8;
    const int wo0 = tid >> 1, wk8 = (tid & 1) * 8;
    uint4 ra[2]; uint4 rwv;

    #define G3_LOAD(cc) do { \
        _Pragma("unroll") \
        for (int s = 0; s < 2; s++) { \
            int row = row0 + s * 8; \
            int ch = (cc) + row; \
            if (ch < 64) { \
                const float* src = &xb[(size_t)ch * HWSZ + p0 + cb0]; \
                float4 v0 = *(const float4*)src; \
                float4 v1 = *(const float4*)(src + 4); \
                ra[s].x = packh2(v0.x, v0.y); ra[s].y = packh2(v0.z, v0.w); \
                ra[s].z = packh2(v1.x, v1.y); ra[s].w = packh2(v1.z, v1.w); \
            } else { \
                ra[s] = *(const uint4*)&rbh[(size_t)(ch - 64) * HWSZ + p0 + cb0]; \
            } \
        } \
        if (tid < 128) rwv = *(const uint4*)&g_wfh[wo0 * 128 + (cc) + wk8]; \
    } while (0)
    #define G3_STORE(st) do { \
        _Pragma("unroll") \
        for (int s = 0; s < 2; s++) \
            *(uint4*)&sA[st][row0 + s * 8][cb0] = ra[s]; \
        if (tid < 128) *(uint4*)&sW[st][wo0][wk8] = rwv; \
    } while (0)

    uint32_t saddrA = (uint32_t)__cvta_generic_to_shared(&sA[0][0][0]);
    uint32_t saddrW = (uint32_t)__cvta_generic_to_shared(&sW[0][0][0]);
    const int q = lane >> 3, r = lane & 7;
    const uint32_t aoff = (uint32_t)((((q & 1) * 8 + r) * 264 + (q >> 1) * 8) * 2);
    const uint32_t woff0 = (uint32_t)(((obase + (q & 1) * 8 + r) * 24 + (q >> 1) * 8) * 2);
    const uint32_t woff1 = woff0 + 16 * 24 * 2;

    G3_LOAD(0); G3_STORE(0);
    __syncthreads();
    int cur = 0;
    for (int cc = 0; cc < 128; cc += 16) {
        const bool hasnext = (cc + 16 < 128);
        if (hasnext) G3_LOAD(cc + 16);
        uint32_t baA = saddrA + (uint32_t)(cur * 16 * 264 * 2);
        uint32_t baW = saddrW + (uint32_t)(cur * 64 * 24 * 2);
        uint32_t wa0[4], wa1[4];
        ldsm4(wa0, baW + woff0);
        ldsm4(wa1, baW + woff1);
        #pragma unroll
        for (int j = 0; j < 4; j++) {
            uint32_t ab[4];
            ldsm4t(ab, baA + aoff + (uint32_t)((pbase + j * 16) * 2));
            mma_f16(acc[0][2 * j],     wa0, ab[0], ab[1]);
            mma_f16(acc[1][2 * j],     wa1, ab[0], ab[1]);
            mma_f16(acc[0][2 * j + 1], wa0, ab[2], ab[3]);
            mma_f16(acc[1][2 * j + 1], wa1, ab[2], ab[3]);
        }
        if (hasnext) G3_STORE(cur ^ 1);
        __syncthreads();
        cur ^= 1;
    }
    float* ob = out + (size_t)b * 64 * HWSZ;
    #pragma unroll
    for (int mt = 0; mt < 2; mt++) {
        int o1 = obase + mt * 16 + gid;
        float bia = bf[o1], bib = bf[o1 + 8];
        #pragma unroll
        for (int nt = 0; nt < 8; nt++) {
            int p = p0 + pbase + nt * 8 + 2 * tig;
            *(float2*)&ob[(size_t)o1 * HWSZ + p] = make_float2(acc[mt][nt].x + bia, acc[mt][nt].y + bia);
            *(float2*)&ob[(size_t)(o1 + 8) * HWSZ + p] = make_float2(acc[mt][nt].z + bib, acc[mt][nt].w + bib);
        }
    }
}

extern "C" void kernel_launch(void* const* d_in, const int* in_sizes, int n_in,
                              void* d_out, int out_size) {
    const float* x     = (const float*)d_in[0];
    const float* w1    = (const float*)d_in[1];
    const float* b1    = (const float*)d_in[2];
    const float* gamma = (const float*)d_in[3];
    const float* beta  = (const float*)d_in[4];
    const float* w2    = (const float*)d_in[5];
    const float* b2    = (const float*)d_in[6];
    const float* g1    = (const float*)d_in[7];
    const float* gb1   = (const float*)d_in[8];
    const float* g2    = (const float*)d_in[9];
    const float* gb2   = (const float*)d_in[10];
    const float* wf    = (const float*)d_in[11];
    const float* bf    = (const float*)d_in[12];
    float* out = (float*)d_out;

    // launch order: k_gemm2 sits at profiled launch index 3
    k_prep<<<128, 256>>>(w1, w2, wf);
    k_dwt<<<dim3(17, 512), 256>>>(x);
    k_gemm1<<<dim3(135, 8), 256>>>(b1);
    k_gemm2<<<dim3(269, 8), 256>>>(b2, gamma, beta, g1, gb1, g2, gb2);
    k_idwt<<<dim3(32, 512), 256>>>();
    k_final<<<dim3(256, 8), 256>>>(x, bf, out);
}

// round 15
// speedup vs baseline: 1.1038x; 1.1038x over previous
#include <cuda_runtime.h>
#include <cuda_fp16.h>
#include <stdint.h>
#include <math.h>

#define BB 8
#define CC 64
#define HH 256
#define WW 256
#define OHH 131
#define OWW 131
#define PP (OHH*OWW)      /* 17161 */
#define PSTRH 17168       /* fp16 channel stride (16B rows) */
#define HWSZ (HH*WW)

// db4 filters
__constant__ float DEC_LO[8] = {
    -0.010597401784997278f, 0.032883011666982945f, 0.030841381835986965f,
    -0.18703481171888114f, -0.02798376941698385f, 0.6308807679295904f,
    0.7148465705525415f, 0.23037781330885523f };
__constant__ float DEC_HI[8] = {
    -0.23037781330885523f, 0.7148465705525415f, -0.6308807679295904f,
    -0.02798376941698385f, 0.18703481171888114f, 0.030841381835986965f,
    -0.032883011666982945f, -0.010597401784997278f };

// Scratch
__device__ __align__(16) __half g_ffh[(size_t)BB*256*PSTRH + 8192];
__device__ __align__(16) __half g_zh[(size_t)BB*128*PSTRH + 8192];
__device__ __align__(16) __half g_reconh[(size_t)BB*64*HWSZ];
__device__ __align__(16) __half g_w1h[128*256];
__device__ __align__(16) __half g_w2h[256*128];
__device__ __align__(16) __half g_wfh[64*128];
__device__ float g_stats[128];
__device__ float g_density[512];
__device__ float g_gates[32];

// ---- helpers ----
__device__ __forceinline__ void mma_f16(float4& d, const uint32_t a[4], uint32_t b0, uint32_t b1) {
    asm volatile("mma.sync.aligned.m16n8k16.row.col.f32.f16.f16.f32 "
        "{%0,%1,%2,%3}, {%4,%5,%6,%7}, {%8,%9}, {%0,%1,%2,%3};"
        : "+f"(d.x), "+f"(d.y), "+f"(d.z), "+f"(d.w)
        : "r"(a[0]), "r"(a[1]), "r"(a[2]), "r"(a[3]), "r"(b0), "r"(b1));
}
__device__ __forceinline__ void ldsm4(uint32_t r[4], uint32_t a) {
    asm volatile("ldmatrix.sync.aligned.m8n8.x4.shared.b16 {%0,%1,%2,%3}, [%4];"
        : "=r"(r[0]), "=r"(r[1]), "=r"(r[2]), "=r"(r[3]) : "r"(a));
}
__device__ __forceinline__ void ldsm4t(uint32_t r[4], uint32_t a) {
    asm volatile("ldmatrix.sync.aligned.m8n8.x4.trans.shared.b16 {%0,%1,%2,%3}, [%4];"
        : "=r"(r[0]), "=r"(r[1]), "=r"(r[2]), "=r"(r[3]) : "r"(a));
}
__device__ __forceinline__ uint32_t packh2(float a, float b) {
    __half2 h = __floats2half2_rn(a, b);
    return *(uint32_t*)&h;
}
// packed f32x2
__device__ __forceinline__ uint64_t pk2(float lo, float hi) {
    uint64_t r; asm("mov.b64 %0, {%1,%2};" : "=l"(r) : "f"(lo), "f"(hi)); return r;
}
__device__ __forceinline__ void upk2(uint64_t v, float& lo, float& hi) {
    asm("mov.b64 {%0,%1}, %2;" : "=f"(lo), "=f"(hi) : "l"(v));
}
__device__ __forceinline__ uint64_t fma2(uint64_t a, uint64_t b, uint64_t c) {
    uint64_t d; asm("fma.rn.f32x2 %0, %1, %2, %3;" : "=l"(d) : "l"(a), "l"(b), "l"(c)); return d;
}

// ---------------- K0: prep (single kernel) ----------------
__global__ void k_prep(const float* __restrict__ w1, const float* __restrict__ w2,
                       const float* __restrict__ wf) {
    int i = blockIdx.x * 256 + threadIdx.x;     // 32768
    g_w1h[i] = __float2half(w1[i]);
    g_w2h[i] = __float2half(w2[i]);
    if (i < 8192) g_wfh[i] = __float2half(wf[i]);
    if (i < 512) g_density[i] = 0.f;
    if (i < 128) g_stats[i] = 0.f;
}

// ---------------- K2: DWT2 -> g_ffh + inline density (f32x2 math) ----------------
__global__ void __launch_bounds__(256) k_dwt(const float* __restrict__ x) {
    const int gi0 = blockIdx.x * 8;
    const int bc = blockIdx.y;
    __shared__ float sIn[22][272];
    __shared__ float sT[2][22][132];
    const float* xp = x + (size_t)bc * HWSZ;

    int cnt = 0;
    const bool owner = (blockIdx.x < 16);
    for (int idx = threadIdx.x; idx < 22 * 64; idx += 256) {
        int r = idx >> 6, q = idx & 63;
        int m = 2 * gi0 - 6 + r;
        m = (m < 0) ? (-1 - m) : ((m > 255) ? (511 - m) : m);
        float4 v = *(const float4*)&xp[m * 256 + 4 * q];
        *(float4*)&sIn[r][8 + 4 * q] = v;
        if (owner && r >= 6)
            cnt += (v.x != 0.f) + (v.y != 0.f) + (v.z != 0.f) + (v.w != 0.f);
    }
    if (owner) {
        #pragma unroll
        for (int off = 16; off > 0; off >>= 1)
            cnt += __shfl_down_sync(0xffffffffu, cnt, off);
        if ((threadIdx.x & 31) == 0 && cnt > 0)
            atomicAdd(&g_density[bc], (float)cnt);
    }
    for (int idx = threadIdx.x; idx < 22 * 12; idx += 256) {
        int r = idx / 12, e = idx % 12;
        int m = 2 * gi0 - 6 + r;
        m = (m < 0) ? (-1 - m) : ((m > 255) ? (511 - m) : m);
        int col = (e < 6) ? (2 + e) : (258 + e);
        int n = (e < 6) ? (5 - e) : (261 - e);
        sIn[r][col] = xp[m * 256 + n];
    }
    uint64_t cpk[8];
    #pragma unroll
    for (int v = 0; v < 8; v++) cpk[v] = pk2(DEC_LO[7 - v], DEC_HI[7 - v]);
    const uint64_t z2 = pk2(0.f, 0.f);
    __syncthreads();
    for (int idx = threadIdx.x; idx < 22 * 131; idx += 256) {
        int r = idx / 131, j = idx % 131;
        uint64_t acc = z2;
        #pragma unroll
        for (int v = 0; v < 8; v++) {
            float xv = sIn[r][2 * j + v + 2];
            acc = fma2(pk2(xv, xv), cpk[v], acc);
        }
        float lo, hi; upk2(acc, lo, hi);
        sT[0][r][j] = lo; sT[1][r][j] = hi;
    }
    __syncthreads();
    int b = bc >> 6, c = bc & 63;
    __half* base = g_ffh + ((size_t)b * 256 + c) * PSTRH;
    for (int idx = threadIdx.x; idx < 8 * 131; idx += 256) {
        int ii = idx / 131, j = idx % 131;
        int gi = gi0 + ii;
        if (gi < OHH) {
            uint64_t accA = z2, accB = z2;
            #pragma unroll
            for (int u = 0; u < 8; u++) {
                float tl = sT[0][2 * ii + u][j], th = sT[1][2 * ii + u][j];
                accA = fma2(pk2(tl, tl), cpk[u], accA);
                accB = fma2(pk2(th, th), cpk[u], accB);
            }
            float aa, da, ad, dd;
            upk2(accA, aa, da); upk2(accB, ad, dd);
            int p = gi * OWW + j;
            base[p] = __float2half(aa);
            base[(size_t)64 * PSTRH + p] = __float2half(da);
            base[(size_t)128 * PSTRH + p] = __float2half(ad);
            base[(size_t)192 * PSTRH + p] = __float2half(dd);
        }
    }
}

// ---------------- K3: gemm1 (fp16 mma + ldmatrix, cp.async 4-stage), z -> fp16 ----------------
#define G1_SAH 2176
#define G1_SWH 3072

__global__ void __launch_bounds__(256) k_gemm1(const float* __restrict__ b1) {
    __shared__ __half sA[4][16][136];
    __shared__ __half sW[4][128][24];
    const int b = blockIdx.y;
    const int p0 = blockIdx.x * 128;
    const int tid = threadIdx.x;
    const __half* ffb = g_ffh + (size_t)b * 256 * PSTRH;
    uint32_t saddrA = (uint32_t)__cvta_generic_to_shared(&sA[0][0][0]);
    uint32_t saddrW = (uint32_t)__cvta_generic_to_shared(&sW[0][0][0]);

    const int ar_ = tid >> 4, ac8 = (tid & 15) * 8;
    const int wo_ = tid >> 1, wk8 = (tid & 1) * 8;

    #define G1_ISSUE(stage, qc) do { \
        const __half* srcA = ffb + (size_t)((qc) + ar_) * PSTRH + p0 + ac8; \
        uint32_t dstA = saddrA + (uint32_t)(((stage) * G1_SAH + ar_ * 136 + ac8) * 2); \
        int rem = PP - (p0 + ac8); \
        int bytes = (rem >= 8) ? 16 : ((rem > 0) ? rem * 2 : 0); \
        asm volatile("cp.async.ca.shared.global [%0], [%1], 16, %2;" \
                     :: "r"(dstA), "l"(srcA), "r"(bytes)); \
        const __half* srcW = g_w1h + wo_ * 256 + (qc) + wk8; \
        uint32_t dstW = saddrW + (uint32_t)(((stage) * G1_SWH + wo_ * 24 + wk8) * 2); \
        asm volatile("cp.async.ca.shared.global [%0], [%1], 16;" \
                     :: "r"(dstW), "l"(srcW)); \
    } while (0)

    G1_ISSUE(0, 0);   asm volatile("cp.async.commit_group;" ::: "memory");
    G1_ISSUE(1, 16);  asm volatile("cp.async.commit_group;" ::: "memory");
    G1_ISSUE(2, 32);  asm volatile("cp.async.commit_group;" ::: "memory");

    const int w = tid >> 5, lane = tid & 31;
    const int gid = lane >> 2, tig = lane & 3;
    const int obase = (w >> 1) * 32, pbase = (w & 1) * 64;
    const int q = lane >> 3, r = lane & 7;
    const uint32_t aoff = (uint32_t)((((q & 1) * 8 + r) * 136 + (q >> 1) * 8) * 2);
    const uint32_t woff0 = (uint32_t)(((obase + (q & 1) * 8 + r) * 24 + (q >> 1) * 8) * 2);
    const uint32_t woff1 = woff0 + 16 * 24 * 2;
    float4 acc[2][8] = {};
    const bool fullA = (p0 + 128 <= PP);

    for (int i = 0; i < 16; i++) {
        asm volatile("cp.async.wait_group 2;" ::: "memory");
        __syncthreads();
        if (i + 3 < 16) { G1_ISSUE((i + 3) & 3, (i + 3) * 16); }
        asm volatile("cp.async.commit_group;" ::: "memory");
        uint32_t baA = saddrA + (uint32_t)((i & 3) * G1_SAH * 2);
        uint32_t baW = saddrW + (uint32_t)((i & 3) * G1_SWH * 2);
        uint32_t wa0[4], wa1[4];
        ldsm4(wa0, baW + woff0);
        ldsm4(wa1, baW + woff1);
        #pragma unroll
        for (int j = 0; j < 4; j++) {
            uint32_t ab[4];
            ldsm4t(ab, baA + aoff + (uint32_t)((pbase + j * 16) * 2));
            mma_f16(acc[0][2 * j],     wa0, ab[0], ab[1]);
            mma_f16(acc[1][2 * j],     wa1, ab[0], ab[1]);
            mma_f16(acc[0][2 * j + 1], wa0, ab[2], ab[3]);
            mma_f16(acc[1][2 * j + 1], wa1, ab[2], ab[3]);
        }
    }
    // epilogue: +bias, GN stats from fp32 accs, store z as fp16
    float s1[2] = {0.f, 0.f}, s2[2] = {0.f, 0.f};
    __half* zb = g_zh + (size_t)b * 128 * PSTRH;
    #pragma unroll
    for (int mt = 0; mt < 2; mt++) {
        int o1 = obase + mt * 16 + gid;
        float bia = b1[o1], bib = b1[o1 + 8];
        #pragma unroll
        for (int nt = 0; nt < 8; nt++) {
            int p = p0 + pbase + nt * 8 + 2 * tig;
            float vx = acc[mt][nt].x + bia, vy = acc[mt][nt].y + bia;
            float vz = acc[mt][nt].z + bib, vw = acc[mt][nt].w + bib;
            if (fullA) {
                s1[mt] += vx + vy + vz + vw;
                s2[mt] += vx*vx + vy*vy + vz*vz + vw*vw;
                *(__half2*)&zb[(size_t)o1 * PSTRH + p] = __floats2half2_rn(vx, vy);
                *(__half2*)&zb[(size_t)(o1 + 8) * PSTRH + p] = __floats2half2_rn(vz, vw);
            } else {
                if (p < PP)     { zb[(size_t)o1*PSTRH + p] = __float2half_rn(vx);     zb[(size_t)(o1+8)*PSTRH + p] = __float2half_rn(vz);     s1[mt] += vx + vz; s2[mt] += vx*vx + vz*vz; }
                if (p + 1 < PP) { zb[(size_t)o1*PSTRH + p + 1] = __float2half_rn(vy); zb[(size_t)(o1+8)*PSTRH + p + 1] = __float2half_rn(vw); s1[mt] += vy + vw; s2[mt] += vy*vy + vw*vw; }
            }
        }
    }
    #pragma unroll
    for (int off = 16; off > 0; off >>= 1) {
        s1[0] += __shfl_down_sync(0xffffffffu, s1[0], off);
        s2[0] += __shfl_down_sync(0xffffffffu, s2[0], off);
        s1[1] += __shfl_down_sync(0xffffffffu, s1[1], off);
        s2[1] += __shfl_down_sync(0xffffffffu, s2[1], off);
    }
    if (lane == 0) {
        int g0 = (w >> 1) * 2;
        atomicAdd(&g_stats[(b * 8 + g0) * 2],     s1[0]);
        atomicAdd(&g_stats[(b * 8 + g0) * 2 + 1], s2[0]);
        atomicAdd(&g_stats[(b * 8 + g0 + 1) * 2],     s1[1]);
        atomicAdd(&g_stats[(b * 8 + g0 + 1) * 2 + 1], s2[1]);
    }
}

// ---------------- K4: GN finalize + GELU in place on z; gates ----------------
__global__ void __launch_bounds__(256) k_gn(const float* __restrict__ gamma,
                                            const float* __restrict__ beta,
                                            const float* __restrict__ g1,
                                            const float* __restrict__ gb1,
                                            const float* __restrict__ g2,
                                            const float* __restrict__ gb2) {
    const int ch = blockIdx.x;    // 0..127
    const int b = blockIdx.y;
    const int g = ch >> 4;
    float s1 = g_stats[(b * 8 + g) * 2], s2 = g_stats[(b * 8 + g) * 2 + 1];
    float invN = 1.f / (16.f * (float)PP);
    float mu = s1 * invN;
    float rs = rsqrtf(s2 * invN - mu * mu + 1e-5f);
    float sc = rs * gamma[ch];
    float sh = beta[ch] - mu * sc;

    uint4* zp = (uint4*)(g_zh + ((size_t)b * 128 + ch) * PSTRH);
    for (int i = threadIdx.x; i < PSTRH / 8; i += 256) {
        uint4 v = zp[i];
        __half2* h = (__half2*)&v;
        #pragma unroll
        for (int j = 0; j < 4; j++) {
            float2 f = __half22float2(h[j]);
            f.x = f.x * sc + sh; f.x = 0.5f * f.x * (1.f + erff(f.x * 0.70710678118654752f));
            f.y = f.y * sc + sh; f.y = 0.5f * f.y * (1.f + erff(f.y * 0.70710678118654752f));
            h[j] = __floats2half2_rn(f.x, f.y);
        }
        zp[i] = v;
    }
    // gates (one block per batch)
    if (ch == 0 && threadIdx.x < 32) {
        int lane = threadIdx.x;
        __shared__ float sH[16];
        const float invHW = 1.f / (float)HWSZ;
        if (lane < 16) {
            float s = gb1[lane];
            #pragma unroll 4
            for (int c = 0; c < 64; c++) s += (g_density[b * 64 + c] * invHW) * g1[lane * 64 + c];
            sH[lane] = fmaxf(s, 0.f);
        }
        __syncwarp();
        if (lane < 4) {
            float s = gb2[lane];
            #pragma unroll
            for (int i = 0; i < 16; i++) s += sH[i] * g2[lane * 16 + i];
            g_gates[b * 4 + lane] = 1.f / (1.f + expf(-s));
        }
    }
}

// ---------------- K5: gemm2 = gemm1-template: gated = (zg @ w2^T + b2) * gate ----------------
__global__ void __launch_bounds__(256) k_gemm2(const float* __restrict__ b2) {
    __shared__ __half sA[4][16][136];
    __shared__ __half sW[4][128][24];
    const int b = blockIdx.z;
    const int ob = blockIdx.y * 128;
    const int p0 = blockIdx.x * 128;
    const int tid = threadIdx.x;
    const __half* zgb = g_zh + (size_t)b * 128 * PSTRH;
    uint32_t saddrA = (uint32_t)__cvta_generic_to_shared(&sA[0][0][0]);
    uint32_t saddrW = (uint32_t)__cvta_generic_to_shared(&sW[0][0][0]);

    const int ar_ = tid >> 4, ac8 = (tid & 15) * 8;
    const int wo_ = tid >> 1, wk8 = (tid & 1) * 8;

    #define G2_ISSUE(stage, qc) do { \
        const __half* srcA = zgb + (size_t)((qc) + ar_) * PSTRH + p0 + ac8; \
        uint32_t dstA = saddrA + (uint32_t)(((stage) * G1_SAH + ar_ * 136 + ac8) * 2); \
        int rem = PP - (p0 + ac8); \
        int bytes = (rem >= 8) ? 16 : ((rem > 0) ? rem * 2 : 0); \
        asm volatile("cp.async.ca.shared.global [%0], [%1], 16, %2;" \
                     :: "r"(dstA), "l"(srcA), "r"(bytes)); \
        const __half* srcW = g_w2h + (ob + wo_) * 128 + (qc) + wk8; \
        uint32_t dstW = saddrW + (uint32_t)(((stage) * G1_SWH + wo_ * 24 + wk8) * 2); \
        asm volatile("cp.async.ca.shared.global [%0], [%1], 16;" \
                     :: "r"(dstW), "l"(srcW)); \
    } while (0)

    G2_ISSUE(0, 0);   asm volatile("cp.async.commit_group;" ::: "memory");
    G2_ISSUE(1, 16);  asm volatile("cp.async.commit_group;" ::: "memory");
    G2_ISSUE(2, 32);  asm volatile("cp.async.commit_group;" ::: "memory");

    const int w = tid >> 5, lane = tid & 31;
    const int gid = lane >> 2, tig = lane & 3;
    const int obase = (w >> 1) * 32, pbase = (w & 1) * 64;
    const int q = lane >> 3, r = lane & 7;
    const uint32_t aoff = (uint32_t)((((q & 1) * 8 + r) * 136 + (q >> 1) * 8) * 2);
    const uint32_t woff0 = (uint32_t)(((obase + (q & 1) * 8 + r) * 24 + (q >> 1) * 8) * 2);
    const uint32_t woff1 = woff0 + 16 * 24 * 2;
    float4 acc[2][8] = {};
    const bool fullA = (p0 + 128 <= PP);

    for (int i = 0; i < 8; i++) {
        asm volatile("cp.async.wait_group 2;" ::: "memory");
        __syncthreads();
        if (i + 3 < 8) { G2_ISSUE((i + 3) & 3, (i + 3) * 16); }
        asm volatile("cp.async.commit_group;" ::: "memory");
        uint32_t baA = saddrA + (uint32_t)((i & 3) * G1_SAH * 2);
        uint32_t baW = saddrW + (uint32_t)((i & 3) * G1_SWH * 2);
        uint32_t wa0[4], wa1[4];
        ldsm4(wa0, baW + woff0);
        ldsm4(wa1, baW + woff1);
        #pragma unroll
        for (int j = 0; j < 4; j++) {
            uint32_t ab[4];
            ldsm4t(ab, baA + aoff + (uint32_t)((pbase + j * 16) * 2));
            mma_f16(acc[0][2 * j],     wa0, ab[0], ab[1]);
            mma_f16(acc[1][2 * j],     wa1, ab[0], ab[1]);
            mma_f16(acc[0][2 * j + 1], wa0, ab[2], ab[3]);
            mma_f16(acc[1][2 * j + 1], wa1, ab[2], ab[3]);
        }
    }
    // epilogue: +bias, *gate, store fp16 gated coeffs
    __half* gbuf = g_ffh + (size_t)b * 256 * PSTRH;
    #pragma unroll
    for (int mt = 0; mt < 2; mt++) {
        int o1 = ob + obase + mt * 16 + gid;
        float ga = g_gates[b * 4 + (o1 >> 6)];
        float gb_ = g_gates[b * 4 + ((o1 + 8) >> 6)];
        float bia = b2[o1], bib = b2[o1 + 8];
        #pragma unroll
        for (int nt = 0; nt < 8; nt++) {
            int p = p0 + pbase + nt * 8 + 2 * tig;
            float vx = (acc[mt][nt].x + bia) * ga, vy = (acc[mt][nt].y + bia) * ga;
            float vz = (acc[mt][nt].z + bib) * gb_, vw = (acc[mt][nt].w + bib) * gb_;
            if (fullA) {
                *(__half2*)&gbuf[(size_t)o1 * PSTRH + p] = __floats2half2_rn(vx, vy);
                *(__half2*)&gbuf[(size_t)(o1 + 8) * PSTRH + p] = __floats2half2_rn(vz, vw);
            } else {
                if (p < PP)     { gbuf[(size_t)o1*PSTRH + p] = __float2half_rn(vx);     gbuf[(size_t)(o1+8)*PSTRH + p] = __float2half_rn(vz); }
                if (p + 1 < PP) { gbuf[(size_t)o1*PSTRH + p + 1] = __float2half_rn(vy); gbuf[(size_t)(o1+8)*PSTRH + p + 1] = __float2half_rn(vw); }
            }
        }
    }
}

// ---------------- K6: IDWT2 -> g_reconh (f32x2 math) ----------------
__global__ void __launch_bounds__(256) k_idwt() {
    int tile = blockIdx.x;
    int bc = blockIdx.y;
    int h0 = (tile >> 2) * 32;
    int w0 = (tile & 3) * 64;
    int b = bc >> 6, c = bc & 63;
    __shared__ float scoef[4][19][36];
    __shared__ float stmp[4][19][68];
    const __half* gb = g_ffh + ((size_t)b * 256 + c) * PSTRH;
    int ib0 = h0 >> 1, jb0 = w0 >> 1;

    for (int idx = threadIdx.x; idx < 4 * 19 * 35; idx += 256) {
        int k = idx / (19 * 35); int rem = idx % (19 * 35);
        int il = rem / 35, jl = rem % 35;
        scoef[k][il][jl] = __half2float(gb[(size_t)k * 64 * PSTRH + (ib0 + il) * OWW + jb0 + jl]);
    }
    uint64_t qlo[4], qhi[4];
    #pragma unroll
    for (int t = 0; t < 4; t++) {
        qlo[t] = pk2(DEC_LO[2 * t + 1], DEC_LO[2 * t]);
        qhi[t] = pk2(DEC_HI[2 * t + 1], DEC_HI[2 * t]);
    }
    const uint64_t z2 = pk2(0.f, 0.f);
    __syncthreads();
    for (int s = threadIdx.x; s < 19 * 16; s += 256) {
        int il = s >> 4, ws = s & 15;
        int wl = ws * 4, jb = wl >> 1;
        #pragma unroll
        for (int k = 0; k < 4; k++) {
            const uint64_t* qq = (k < 2) ? qlo : qhi;
            float c0 = scoef[k][il][jb],     c1 = scoef[k][il][jb + 1];
            float c2 = scoef[k][il][jb + 2], c3 = scoef[k][il][jb + 3];
            float c4 = scoef[k][il][jb + 4];
            uint64_t o01 = z2, o23 = z2;
            o01 = fma2(pk2(c0, c0), qq[0], o01);
            o01 = fma2(pk2(c1, c1), qq[1], o01);
            o01 = fma2(pk2(c2, c2), qq[2], o01);
            o01 = fma2(pk2(c3, c3), qq[3], o01);
            o23 = fma2(pk2(c1, c1), qq[0], o23);
            o23 = fma2(pk2(c2, c2), qq[1], o23);
            o23 = fma2(pk2(c3, c3), qq[2], o23);
            o23 = fma2(pk2(c4, c4), qq[3], o23);
            float a0, a1, a2, a3;
            upk2(o01, a0, a1); upk2(o23, a2, a3);
            stmp[k][il][wl + 0] = a0;
            stmp[k][il][wl + 1] = a1;
            stmp[k][il][wl + 2] = a2;
            stmp[k][il][wl + 3] = a3;
        }
    }
    __syncthreads();
    __half* rb = g_reconh + ((size_t)b * 64 + c) * HWSZ;
    for (int s = threadIdx.x; s < 512; s += 256) {
        int wlh = s & 63, hs = s >> 6;
        int hb = hs * 4, ib = hb >> 1;
        uint64_t acc01 = z2, acc23 = z2;
        #pragma unroll
        for (int k = 0; k < 4; k++) {
            const uint64_t* rr = (k & 1) ? qhi : qlo;
            uint64_t tp[5];
            #pragma unroll
            for (int m = 0; m < 5; m++) {
                float tv = stmp[k][ib + m][wlh];
                tp[m] = pk2(tv, tv);
            }
            #pragma unroll
            for (int m = 0; m < 4; m++) {
                acc01 = fma2(tp[m],     rr[m], acc01);
                acc23 = fma2(tp[m + 1], rr[m], acc23);
            }
        }
        float a0, a1, a2, a3;
        upk2(acc01, a0, a1); upk2(acc23, a2, a3);
        rb[(h0 + hb + 0) * WW + w0 + wlh] = __float2half(a0);
        rb[(h0 + hb + 1) * WW + w0 + wlh] = __float2half(a1);
        rb[(h0 + hb + 2) * WW + w0 + wlh] = __float2half(a2);
        rb[(h0 + hb + 3) * WW + w0 + wlh] = __float2half(a3);
    }
}

// ---------------- K7: fused = [x, recon] @ wf^T + bf (fp16 mma) ----------------
__global__ void __launch_bounds__(256) k_final(const float* __restrict__ x,
                                               const float* __restrict__ bf,
                                               float* __restrict__ out) {
    const int b = blockIdx.y;
    const int p0 = blockIdx.x * 256;
    __shared__ __half sW[2][64][24];
    __shared__ __half sA[2][16][264];
    const int tid = threadIdx.x;
    const int w = tid >> 5, lane = tid & 31;
    const int gid = lane >> 2, tig = lane & 3;
    const int obase = (w >> 2) * 32, pbase = (w & 3) * 64;
    float4 acc[2][8] = {};
    const float* xb = x + (size_t)b * 64 * HWSZ;
    const __half* rbh = g_reconh + (size_t)b * 64 * HWSZ;

    const int row0 = tid >> 5, cb0 = (tid & 31) * 8;
    const int wo0 = tid >> 1, wk8 = (tid & 1) * 8;
    uint4 ra[2]; uint4 rwv;

    #define G3_LOAD(cc) do { \
        _Pragma("unroll") \
        for (int s = 0; s < 2; s++) { \
            int row = row0 + s * 8; \
            int ch = (cc) + row; \
            if (ch < 64) { \
                const float* src = &xb[(size_t)ch * HWSZ + p0 + cb0]; \
                float4 v0 = *(const float4*)src; \
                float4 v1 = *(const float4*)(src + 4); \
                ra[s].x = packh2(v0.x, v0.y); ra[s].y = packh2(v0.z, v0.w); \
                ra[s].z = packh2(v1.x, v1.y); ra[s].w = packh2(v1.z, v1.w); \
            } else { \
                ra[s] = *(const uint4*)&rbh[(size_t)(ch - 64) * HWSZ + p0 + cb0]; \
            } \
        } \
        if (tid < 128) rwv = *(const uint4*)&g_wfh[wo0 * 128 + (cc) + wk8]; \
    } while (0)
    #define G3_STORE(st) do { \
        _Pragma("unroll") \
        for (int s = 0; s < 2; s++) \
            *(uint4*)&sA[st][row0 + s * 8][cb0] = ra[s]; \
        if (tid < 128) *(uint4*)&sW[st][wo0][wk8] = rwv; \
    } while (0)

    uint32_t saddrA = (uint32_t)__cvta_generic_to_shared(&sA[0][0][0]);
    uint32_t saddrW = (uint32_t)__cvta_generic_to_shared(&sW[0][0][0]);
    const int q = lane >> 3, r = lane & 7;
    const uint32_t aoff = (uint32_t)((((q & 1) * 8 + r) * 264 + (q >> 1) * 8) * 2);
    const uint32_t woff0 = (uint32_t)(((obase + (q & 1) * 8 + r) * 24 + (q >> 1) * 8) * 2);
    const uint32_t woff1 = woff0 + 16 * 24 * 2;

    G3_LOAD(0); G3_STORE(0);
    __syncthreads();
    int cur = 0;
    for (int cc = 0; cc < 128; cc += 16) {
        const bool hasnext = (cc + 16 < 128);
        if (hasnext) G3_LOAD(cc + 16);
        uint32_t baA = saddrA + (uint32_t)(cur * 16 * 264 * 2);
        uint32_t baW = saddrW + (uint32_t)(cur * 64 * 24 * 2);
        uint32_t wa0[4], wa1[4];
        ldsm4(wa0, baW + woff0);
        ldsm4(wa1, baW + woff1);
        #pragma unroll
        for (int j = 0; j < 4; j++) {
            uint32_t ab[4];
            ldsm4t(ab, baA + aoff + (uint32_t)((pbase + j * 16) * 2));
            mma_f16(acc[0][2 * j],     wa0, ab[0], ab[1]);
            mma_f16(acc[1][2 * j],     wa1, ab[0], ab[1]);
            mma_f16(acc[0][2 * j + 1], wa0, ab[2], ab[3]);
            mma_f16(acc[1][2 * j + 1], wa1, ab[2], ab[3]);
        }
        if (hasnext) G3_STORE(cur ^ 1);
        __syncthreads();
        cur ^= 1;
    }
    float* ob = out + (size_t)b * 64 * HWSZ;
    #pragma unroll
    for (int mt = 0; mt < 2; mt++) {
        int o1 = obase + mt * 16 + gid;
        float bia = bf[o1], bib = bf[o1 + 8];
        #pragma unroll
        for (int nt = 0; nt < 8; nt++) {
            int p = p0 + pbase + nt * 8 + 2 * tig;
            *(float2*)&ob[(size_t)o1 * HWSZ + p] = make_float2(acc[mt][nt].x + bia, acc[mt][nt].y + bia);
            *(float2*)&ob[(size_t)(o1 + 8) * HWSZ + p] = make_float2(acc[mt][nt].z + bib, acc[mt][nt].w + bib);
        }
    }
}

extern "C" void kernel_launch(void* const* d_in, const int* in_sizes, int n_in,
                              void* d_out, int out_size) {
    const float* x     = (const float*)d_in[0];
    const float* w1    = (const float*)d_in[1];
    const float* b1    = (const float*)d_in[2];
    const float* gamma = (const float*)d_in[3];
    const float* beta  = (const float*)d_in[4];
    const float* w2    = (const float*)d_in[5];
    const float* b2    = (const float*)d_in[6];
    const float* g1    = (const float*)d_in[7];
    const float* gb1   = (const float*)d_in[8];
    const float* g2    = (const float*)d_in[9];
    const float* gb2   = (const float*)d_in[10];
    const float* wf    = (const float*)d_in[11];
    const float* bf    = (const float*)d_in[12];
    float* out = (float*)d_out;

    k_prep<<<128, 256>>>(w1, w2, wf);
    k_dwt<<<dim3(17, 512), 256>>>(x);
    k_gemm1<<<dim3(135, 8), 256>>>(b1);
    k_gn<<<dim3(128, 8), 256>>>(gamma, beta, g1, gb1, g2, gb2);
    k_gemm2<<<dim3(135, 2, 8), 256>>>(b2);
    k_idwt<<<dim3(32, 512), 256>>>();
    k_final<<<dim3(256, 8), 256>>>(x, bf, out);
}

// round 16
// speedup vs baseline: 1.1222x; 1.0166x over previous
#include <cuda_runtime.h>
#include <cuda_fp16.h>
#include <stdint.h>
#include <math.h>

#define BB 8
#define CC 64
#define HH 256
#define WW 256
#define OHH 131
#define OWW 131
#define PP (OHH*OWW)      /* 17161 */
#define PSTRH 17168       /* fp16 channel stride (16B rows) */
#define HWSZ (HH*WW)

// db4 filters
__constant__ float DEC_LO[8] = {
    -0.010597401784997278f, 0.032883011666982945f, 0.030841381835986965f,
    -0.18703481171888114f, -0.02798376941698385f, 0.6308807679295904f,
    0.7148465705525415f, 0.23037781330885523f };
__constant__ float DEC_HI[8] = {
    -0.23037781330885523f, 0.7148465705525415f, -0.6308807679295904f,
    -0.02798376941698385f, 0.18703481171888114f, 0.030841381835986965f,
    -0.032883011666982945f, -0.010597401784997278f };

// Scratch
__device__ __align__(16) __half g_ffh[(size_t)BB*256*PSTRH + 8192];  // coeffs then MIXED coeffs
__device__ __align__(16) __half g_zh[(size_t)BB*128*PSTRH + 8192];
__device__ __align__(16) __half g_reconh[(size_t)BB*64*HWSZ];        // mixed recon
__device__ __align__(16) __half g_w1h[128*256];
__device__ __align__(16) __half g_w2fh[256*128];   // wfr-folded w2
__device__ __align__(16) __half g_wfh[64*128];     // only cols 0..63 used (x half)
__device__ float g_b2f[256];                       // wfr-folded b2
__device__ float g_stats[128];
__device__ float g_density[512];
__device__ float g_gates[32];

// ---- helpers ----
__device__ __forceinline__ void mma_f16(float4& d, const uint32_t a[4], uint32_t b0, uint32_t b1) {
    asm volatile("mma.sync.aligned.m16n8k16.row.col.f32.f16.f16.f32 "
        "{%0,%1,%2,%3}, {%4,%5,%6,%7}, {%8,%9}, {%0,%1,%2,%3};"
        : "+f"(d.x), "+f"(d.y), "+f"(d.z), "+f"(d.w)
        : "r"(a[0]), "r"(a[1]), "r"(a[2]), "r"(a[3]), "r"(b0), "r"(b1));
}
__device__ __forceinline__ void ldsm4(uint32_t r[4], uint32_t a) {
    asm volatile("ldmatrix.sync.aligned.m8n8.x4.shared.b16 {%0,%1,%2,%3}, [%4];"
        : "=r"(r[0]), "=r"(r[1]), "=r"(r[2]), "=r"(r[3]) : "r"(a));
}
__device__ __forceinline__ void ldsm4t(uint32_t r[4], uint32_t a) {
    asm volatile("ldmatrix.sync.aligned.m8n8.x4.trans.shared.b16 {%0,%1,%2,%3}, [%4];"
        : "=r"(r[0]), "=r"(r[1]), "=r"(r[2]), "=r"(r[3]) : "r"(a));
}
__device__ __forceinline__ uint32_t packh2(float a, float b) {
    __half2 h = __floats2half2_rn(a, b);
    return *(uint32_t*)&h;
}
// packed f32x2
__device__ __forceinline__ uint64_t pk2(float lo, float hi) {
    uint64_t r; asm("mov.b64 %0, {%1,%2};" : "=l"(r) : "f"(lo), "f"(hi)); return r;
}
__device__ __forceinline__ void upk2(uint64_t v, float& lo, float& hi) {
    asm("mov.b64 {%0,%1}, %2;" : "=f"(lo), "=f"(hi) : "l"(v));
}
__device__ __forceinline__ uint64_t fma2(uint64_t a, uint64_t b, uint64_t c) {
    uint64_t d; asm("fma.rn.f32x2 %0, %1, %2, %3;" : "=l"(d) : "l"(a), "l"(b), "l"(c)); return d;
}

// ---------------- K0: prep — fp16 weights, wfr-folded w2f/b2f, zero accum ----------------
__global__ void k_prep(const float* __restrict__ w1, const float* __restrict__ w2,
                       const float* __restrict__ wf, const float* __restrict__ b2) {
    int i = blockIdx.x * 256 + threadIdx.x;     // 32768
    g_w1h[i] = __float2half(w1[i]);
    // w2f[row=k*64+o][q] = sum_c wf[o][64+c] * w2[k*64+c][q]
    {
        int row = i >> 7, qq = i & 127;
        int k = row >> 6, o = row & 63;
        float s = 0.f;
        #pragma unroll 4
        for (int c = 0; c < 64; c++)
            s += wf[o * 128 + 64 + c] * w2[(k * 64 + c) * 128 + qq];
        g_w2fh[i] = __float2half(s);
    }
    if (i < 8192) g_wfh[i] = __float2half(wf[i]);
    if (i < 256) {
        int k = i >> 6, o = i & 63;
        float s = 0.f;
        #pragma unroll 4
        for (int c = 0; c < 64; c++)
            s += wf[o * 128 + 64 + c] * b2[k * 64 + c];
        g_b2f[i] = s;
    }
    if (i < 512) g_density[i] = 0.f;
    if (i < 128) g_stats[i] = 0.f;
}

// ---------------- K2: DWT2 -> g_ffh + inline density (f32x2 math) ----------------
__global__ void __launch_bounds__(256) k_dwt(const float* __restrict__ x) {
    const int gi0 = blockIdx.x * 8;
    const int bc = blockIdx.y;
    __shared__ float sIn[22][272];
    __shared__ float sT[2][22][132];
    const float* xp = x + (size_t)bc * HWSZ;

    int cnt = 0;
    const bool owner = (blockIdx.x < 16);
    for (int idx = threadIdx.x; idx < 22 * 64; idx += 256) {
        int r = idx >> 6, q = idx & 63;
        int m = 2 * gi0 - 6 + r;
        m = (m < 0) ? (-1 - m) : ((m > 255) ? (511 - m) : m);
        float4 v = *(const float4*)&xp[m * 256 + 4 * q];
        *(float4*)&sIn[r][8 + 4 * q] = v;
        if (owner && r >= 6)
            cnt += (v.x != 0.f) + (v.y != 0.f) + (v.z != 0.f) + (v.w != 0.f);
    }
    if (owner) {
        #pragma unroll
        for (int off = 16; off > 0; off >>= 1)
            cnt += __shfl_down_sync(0xffffffffu, cnt, off);
        if ((threadIdx.x & 31) == 0 && cnt > 0)
            atomicAdd(&g_density[bc], (float)cnt);
    }
    for (int idx = threadIdx.x; idx < 22 * 12; idx += 256) {
        int r = idx / 12, e = idx % 12;
        int m = 2 * gi0 - 6 + r;
        m = (m < 0) ? (-1 - m) : ((m > 255) ? (511 - m) : m);
        int col = (e < 6) ? (2 + e) : (258 + e);
        int n = (e < 6) ? (5 - e) : (261 - e);
        sIn[r][col] = xp[m * 256 + n];
    }
    uint64_t cpk[8];
    #pragma unroll
    for (int v = 0; v < 8; v++) cpk[v] = pk2(DEC_LO[7 - v], DEC_HI[7 - v]);
    const uint64_t z2 = pk2(0.f, 0.f);
    __syncthreads();
    for (int idx = threadIdx.x; idx < 22 * 131; idx += 256) {
        int r = idx / 131, j = idx % 131;
        uint64_t acc = z2;
        #pragma unroll
        for (int v = 0; v < 8; v++) {
            float xv = sIn[r][2 * j + v + 2];
            acc = fma2(pk2(xv, xv), cpk[v], acc);
        }
        float lo, hi; upk2(acc, lo, hi);
        sT[0][r][j] = lo; sT[1][r][j] = hi;
    }
    __syncthreads();
    int b = bc >> 6, c = bc & 63;
    __half* base = g_ffh + ((size_t)b * 256 + c) * PSTRH;
    for (int idx = threadIdx.x; idx < 8 * 131; idx += 256) {
        int ii = idx / 131, j = idx % 131;
        int gi = gi0 + ii;
        if (gi < OHH) {
            uint64_t accA = z2, accB = z2;
            #pragma unroll
            for (int u = 0; u < 8; u++) {
                float tl = sT[0][2 * ii + u][j], th = sT[1][2 * ii + u][j];
                accA = fma2(pk2(tl, tl), cpk[u], accA);
                accB = fma2(pk2(th, th), cpk[u], accB);
            }
            float aa, da, ad, dd;
            upk2(accA, aa, da); upk2(accB, ad, dd);
            int p = gi * OWW + j;
            base[p] = __float2half(aa);
            base[(size_t)64 * PSTRH + p] = __float2half(da);
            base[(size_t)128 * PSTRH + p] = __float2half(ad);
            base[(size_t)192 * PSTRH + p] = __float2half(dd);
        }
    }
}

// ---------------- K3: gemm1 (fp16 mma + ldmatrix, cp.async 4-stage), z -> fp16 ----------------
#define G1_SAH 2176
#define G1_SWH 3072

__global__ void __launch_bounds__(256) k_gemm1(const float* __restrict__ b1) {
    __shared__ __half sA[4][16][136];
    __shared__ __half sW[4][128][24];
    const int b = blockIdx.y;
    const int p0 = blockIdx.x * 128;
    const int tid = threadIdx.x;
    const __half* ffb = g_ffh + (size_t)b * 256 * PSTRH;
    uint32_t saddrA = (uint32_t)__cvta_generic_to_shared(&sA[0][0][0]);
    uint32_t saddrW = (uint32_t)__cvta_generic_to_shared(&sW[0][0][0]);

    const int ar_ = tid >> 4, ac8 = (tid & 15) * 8;
    const int wo_ = tid >> 1, wk8 = (tid & 1) * 8;

    #define G1_ISSUE(stage, qc) do { \
        const __half* srcA = ffb + (size_t)((qc) + ar_) * PSTRH + p0 + ac8; \
        uint32_t dstA = saddrA + (uint32_t)(((stage) * G1_SAH + ar_ * 136 + ac8) * 2); \
        int rem = PP - (p0 + ac8); \
        int bytes = (rem >= 8) ? 16 : ((rem > 0) ? rem * 2 : 0); \
        asm volatile("cp.async.ca.shared.global [%0], [%1], 16, %2;" \
                     :: "r"(dstA), "l"(srcA), "r"(bytes)); \
        const __half* srcW = g_w1h + wo_ * 256 + (qc) + wk8; \
        uint32_t dstW = saddrW + (uint32_t)(((stage) * G1_SWH + wo_ * 24 + wk8) * 2); \
        asm volatile("cp.async.ca.shared.global [%0], [%1], 16;" \
                     :: "r"(dstW), "l"(srcW)); \
    } while (0)

    G1_ISSUE(0, 0);   asm volatile("cp.async.commit_group;" ::: "memory");
    G1_ISSUE(1, 16);  asm volatile("cp.async.commit_group;" ::: "memory");
    G1_ISSUE(2, 32);  asm volatile("cp.async.commit_group;" ::: "memory");

    const int w = tid >> 5, lane = tid & 31;
    const int gid = lane >> 2, tig = lane & 3;
    const int obase = (w >> 1) * 32, pbase = (w & 1) * 64;
    const int q = lane >> 3, r = lane & 7;
    const uint32_t aoff = (uint32_t)((((q & 1) * 8 + r) * 136 + (q >> 1) * 8) * 2);
    const uint32_t woff0 = (uint32_t)(((obase + (q & 1) * 8 + r) * 24 + (q >> 1) * 8) * 2);
    const uint32_t woff1 = woff0 + 16 * 24 * 2;
    float4 acc[2][8] = {};
    const bool fullA = (p0 + 128 <= PP);

    for (int i = 0; i < 16; i++) {
        asm volatile("cp.async.wait_group 2;" ::: "memory");
        __syncthreads();
        if (i + 3 < 16) { G1_ISSUE((i + 3) & 3, (i + 3) * 16); }
        asm volatile("cp.async.commit_group;" ::: "memory");
        uint32_t baA = saddrA + (uint32_t)((i & 3) * G1_SAH * 2);
        uint32_t baW = saddrW + (uint32_t)((i & 3) * G1_SWH * 2);
        uint32_t wa0[4], wa1[4];
        ldsm4(wa0, baW + woff0);
        ldsm4(wa1, baW + woff1);
        #pragma unroll
        for (int j = 0; j < 4; j++) {
            uint32_t ab[4];
            ldsm4t(ab, baA + aoff + (uint32_t)((pbase + j * 16) * 2));
            mma_f16(acc[0][2 * j],     wa0, ab[0], ab[1]);
            mma_f16(acc[1][2 * j],     wa1, ab[0], ab[1]);
            mma_f16(acc[0][2 * j + 1], wa0, ab[2], ab[3]);
            mma_f16(acc[1][2 * j + 1], wa1, ab[2], ab[3]);
        }
    }
    // epilogue: +bias, GN stats from fp32 accs, store z as fp16
    float s1[2] = {0.f, 0.f}, s2[2] = {0.f, 0.f};
    __half* zb = g_zh + (size_t)b * 128 * PSTRH;
    #pragma unroll
    for (int mt = 0; mt < 2; mt++) {
        int o1 = obase + mt * 16 + gid;
        float bia = b1[o1], bib = b1[o1 + 8];
        #pragma unroll
        for (int nt = 0; nt < 8; nt++) {
            int p = p0 + pbase + nt * 8 + 2 * tig;
            float vx = acc[mt][nt].x + bia, vy = acc[mt][nt].y + bia;
            float vz = acc[mt][nt].z + bib, vw = acc[mt][nt].w + bib;
            if (fullA) {
                s1[mt] += vx + vy + vz + vw;
                s2[mt] += vx*vx + vy*vy + vz*vz + vw*vw;
                *(__half2*)&zb[(size_t)o1 * PSTRH + p] = __floats2half2_rn(vx, vy);
                *(__half2*)&zb[(size_t)(o1 + 8) * PSTRH + p] = __floats2half2_rn(vz, vw);
            } else {
                if (p < PP)     { zb[(size_t)o1*PSTRH + p] = __float2half_rn(vx);     zb[(size_t)(o1+8)*PSTRH + p] = __float2half_rn(vz);     s1[mt] += vx + vz; s2[mt] += vx*vx + vz*vz; }
                if (p + 1 < PP) { zb[(size_t)o1*PSTRH + p + 1] = __float2half_rn(vy); zb[(size_t)(o1+8)*PSTRH + p + 1] = __float2half_rn(vw); s1[mt] += vy + vw; s2[mt] += vy*vy + vw*vw; }
            }
        }
    }
    #pragma unroll
    for (int off = 16; off > 0; off >>= 1) {
        s1[0] += __shfl_down_sync(0xffffffffu, s1[0], off);
        s2[0] += __shfl_down_sync(0xffffffffu, s2[0], off);
        s1[1] += __shfl_down_sync(0xffffffffu, s1[1], off);
        s2[1] += __shfl_down_sync(0xffffffffu, s2[1], off);
    }
    if (lane == 0) {
        int g0 = (w >> 1) * 2;
        atomicAdd(&g_stats[(b * 8 + g0) * 2],     s1[0]);
        atomicAdd(&g_stats[(b * 8 + g0) * 2 + 1], s2[0]);
        atomicAdd(&g_stats[(b * 8 + g0 + 1) * 2],     s1[1]);
        atomicAdd(&g_stats[(b * 8 + g0 + 1) * 2 + 1], s2[1]);
    }
}

// ---------------- K4: GN finalize + GELU in place on z; gates ----------------
__global__ void __launch_bounds__(256) k_gn(const float* __restrict__ gamma,
                                            const float* __restrict__ beta,
                                            const float* __restrict__ g1,
                                            const float* __restrict__ gb1,
                                            const float* __restrict__ g2,
                                            const float* __restrict__ gb2) {
    const int ch = blockIdx.x;    // 0..127
    const int b = blockIdx.y;
    const int g = ch >> 4;
    float s1 = g_stats[(b * 8 + g) * 2], s2 = g_stats[(b * 8 + g) * 2 + 1];
    float invN = 1.f / (16.f * (float)PP);
    float mu = s1 * invN;
    float rs = rsqrtf(s2 * invN - mu * mu + 1e-5f);
    float sc = rs * gamma[ch];
    float sh = beta[ch] - mu * sc;

    uint4* zp = (uint4*)(g_zh + ((size_t)b * 128 + ch) * PSTRH);
    for (int i = threadIdx.x; i < PSTRH / 8; i += 256) {
        uint4 v = zp[i];
        __half2* h = (__half2*)&v;
        #pragma unroll
        for (int j = 0; j < 4; j++) {
            float2 f = __half22float2(h[j]);
            f.x = f.x * sc + sh; f.x = 0.5f * f.x * (1.f + erff(f.x * 0.70710678118654752f));
            f.y = f.y * sc + sh; f.y = 0.5f * f.y * (1.f + erff(f.y * 0.70710678118654752f));
            h[j] = __floats2half2_rn(f.x, f.y);
        }
        zp[i] = v;
    }
    // gates (one block per batch)
    if (ch == 0 && threadIdx.x < 32) {
        int lane = threadIdx.x;
        __shared__ float sH[16];
        const float invHW = 1.f / (float)HWSZ;
        if (lane < 16) {
            float s = gb1[lane];
            #pragma unroll 4
            for (int c = 0; c < 64; c++) s += (g_density[b * 64 + c] * invHW) * g1[lane * 64 + c];
            sH[lane] = fmaxf(s, 0.f);
        }
        __syncwarp();
        if (lane < 4) {
            float s = gb2[lane];
            #pragma unroll
            for (int i = 0; i < 16; i++) s += sH[i] * g2[lane * 16 + i];
            g_gates[b * 4 + lane] = 1.f / (1.f + expf(-s));
        }
    }
}

// ---------------- K5: gemm2: mixed = (zg @ w2f^T + b2f) * gate (wfr folded in) ----------------
__global__ void __launch_bounds__(256) k_gemm2() {
    __shared__ __half sA[4][16][136];
    __shared__ __half sW[4][128][24];
    const int b = blockIdx.z;
    const int ob = blockIdx.y * 128;
    const int p0 = blockIdx.x * 128;
    const int tid = threadIdx.x;
    const __half* zgb = g_zh + (size_t)b * 128 * PSTRH;
    uint32_t saddrA = (uint32_t)__cvta_generic_to_shared(&sA[0][0][0]);
    uint32_t saddrW = (uint32_t)__cvta_generic_to_shared(&sW[0][0][0]);

    const int ar_ = tid >> 4, ac8 = (tid & 15) * 8;
    const int wo_ = tid >> 1, wk8 = (tid & 1) * 8;

    #define G2_ISSUE(stage, qc) do { \
        const __half* srcA = zgb + (size_t)((qc) + ar_) * PSTRH + p0 + ac8; \
        uint32_t dstA = saddrA + (uint32_t)(((stage) * G1_SAH + ar_ * 136 + ac8) * 2); \
        int rem = PP - (p0 + ac8); \
        int bytes = (rem >= 8) ? 16 : ((rem > 0) ? rem * 2 : 0); \
        asm volatile("cp.async.ca.shared.global [%0], [%1], 16, %2;" \
                     :: "r"(dstA), "l"(srcA), "r"(bytes)); \
        const __half* srcW = g_w2fh + (ob + wo_) * 128 + (qc) + wk8; \
        uint32_t dstW = saddrW + (uint32_t)(((stage) * G1_SWH + wo_ * 24 + wk8) * 2); \
        asm volatile("cp.async.ca.shared.global [%0], [%1], 16;" \
                     :: "r"(dstW), "l"(srcW)); \
    } while (0)

    G2_ISSUE(0, 0);   asm volatile("cp.async.commit_group;" ::: "memory");
    G2_ISSUE(1, 16);  asm volatile("cp.async.commit_group;" ::: "memory");
    G2_ISSUE(2, 32);  asm volatile("cp.async.commit_group;" ::: "memory");

    const int w = tid >> 5, lane = tid & 31;
    const int gid = lane >> 2, tig = lane & 3;
    const int obase = (w >> 1) * 32, pbase = (w & 1) * 64;
    const int q = lane >> 3, r = lane & 7;
    const uint32_t aoff = (uint32_t)((((q & 1) * 8 + r) * 136 + (q >> 1) * 8) * 2);
    const uint32_t woff0 = (uint32_t)(((obase + (q & 1) * 8 + r) * 24 + (q >> 1) * 8) * 2);
    const uint32_t woff1 = woff0 + 16 * 24 * 2;
    float4 acc[2][8] = {};
    const bool fullA = (p0 + 128 <= PP);

    for (int i = 0; i < 8; i++) {
        asm volatile("cp.async.wait_group 2;" ::: "memory");
        __syncthreads();
        if (i + 3 < 8) { G2_ISSUE((i + 3) & 3, (i + 3) * 16); }
        asm volatile("cp.async.commit_group;" ::: "memory");
        uint32_t baA = saddrA + (uint32_t)((i & 3) * G1_SAH * 2);
        uint32_t baW = saddrW + (uint32_t)((i & 3) * G1_SWH * 2);
        uint32_t wa0[4], wa1[4];
        ldsm4(wa0, baW + woff0);
        ldsm4(wa1, baW + woff1);
        #pragma unroll
        for (int j = 0; j < 4; j++) {
            uint32_t ab[4];
            ldsm4t(ab, baA + aoff + (uint32_t)((pbase + j * 16) * 2));
            mma_f16(acc[0][2 * j],     wa0, ab[0], ab[1]);
            mma_f16(acc[1][2 * j],     wa1, ab[0], ab[1]);
            mma_f16(acc[0][2 * j + 1], wa0, ab[2], ab[3]);
            mma_f16(acc[1][2 * j + 1], wa1, ab[2], ab[3]);
        }
    }
    // epilogue: +b2f, *gate, store fp16 mixed coeffs
    __half* gbuf = g_ffh + (size_t)b * 256 * PSTRH;
    #pragma unroll
    for (int mt = 0; mt < 2; mt++) {
        int o1 = ob + obase + mt * 16 + gid;
        float ga = g_gates[b * 4 + (o1 >> 6)];
        float gb_ = g_gates[b * 4 + ((o1 + 8) >> 6)];
        float bia = g_b2f[o1], bib = g_b2f[o1 + 8];
        #pragma unroll
        for (int nt = 0; nt < 8; nt++) {
            int p = p0 + pbase + nt * 8 + 2 * tig;
            float vx = (acc[mt][nt].x + bia) * ga, vy = (acc[mt][nt].y + bia) * ga;
            float vz = (acc[mt][nt].z + bib) * gb_, vw = (acc[mt][nt].w + bib) * gb_;
            if (fullA) {
                *(__half2*)&gbuf[(size_t)o1 * PSTRH + p] = __floats2half2_rn(vx, vy);
                *(__half2*)&gbuf[(size_t)(o1 + 8) * PSTRH + p] = __floats2half2_rn(vz, vw);
            } else {
                if (p < PP)     { gbuf[(size_t)o1*PSTRH + p] = __float2half_rn(vx);     gbuf[(size_t)(o1+8)*PSTRH + p] = __float2half_rn(vz); }
                if (p + 1 < PP) { gbuf[(size_t)o1*PSTRH + p + 1] = __float2half_rn(vy); gbuf[(size_t)(o1+8)*PSTRH + p + 1] = __float2half_rn(vw); }
            }
        }
    }
}

// ---------------- K6: IDWT2 -> g_reconh (f32x2 math) ----------------
__global__ void __launch_bounds__(256) k_idwt() {
    int tile = blockIdx.x;
    int bc = blockIdx.y;
    int h0 = (tile >> 2) * 32;
    int w0 = (tile & 3) * 64;
    int b = bc >> 6, c = bc & 63;
    __shared__ float scoef[4][19][36];
    __shared__ float stmp[4][19][68];
    const __half* gb = g_ffh + ((size_t)b * 256 + c) * PSTRH;
    int ib0 = h0 >> 1, jb0 = w0 >> 1;

    for (int idx = threadIdx.x; idx < 4 * 19 * 35; idx += 256) {
        int k = idx / (19 * 35); int rem = idx % (19 * 35);
        int il = rem / 35, jl = rem % 35;
        scoef[k][il][jl] = __half2float(gb[(size_t)k * 64 * PSTRH + (ib0 + il) * OWW + jb0 + jl]);
    }
    uint64_t qlo[4], qhi[4];
    #pragma unroll
    for (int t = 0; t < 4; t++) {
        qlo[t] = pk2(DEC_LO[2 * t + 1], DEC_LO[2 * t]);
        qhi[t] = pk2(DEC_HI[2 * t + 1], DEC_HI[2 * t]);
    }
    const uint64_t z2 = pk2(0.f, 0.f);
    __syncthreads();
    for (int s = threadIdx.x; s < 19 * 16; s += 256) {
        int il = s >> 4, ws = s & 15;
        int wl = ws * 4, jb = wl >> 1;
        #pragma unroll
        for (int k = 0; k < 4; k++) {
            const uint64_t* qq = (k < 2) ? qlo : qhi;
            float c0 = scoef[k][il][jb],     c1 = scoef[k][il][jb + 1];
            float c2 = scoef[k][il][jb + 2], c3 = scoef[k][il][jb + 3];
            float c4 = scoef[k][il][jb + 4];
            uint64_t o01 = z2, o23 = z2;
            o01 = fma2(pk2(c0, c0), qq[0], o01);
            o01 = fma2(pk2(c1, c1), qq[1], o01);
            o01 = fma2(pk2(c2, c2), qq[2], o01);
            o01 = fma2(pk2(c3, c3), qq[3], o01);
            o23 = fma2(pk2(c1, c1), qq[0], o23);
            o23 = fma2(pk2(c2, c2), qq[1], o23);
            o23 = fma2(pk2(c3, c3), qq[2], o23);
            o23 = fma2(pk2(c4, c4), qq[3], o23);
            float a0, a1, a2, a3;
            upk2(o01, a0, a1); upk2(o23, a2, a3);
            stmp[k][il][wl + 0] = a0;
            stmp[k][il][wl + 1] = a1;
            stmp[k][il][wl + 2] = a2;
            stmp[k][il][wl + 3] = a3;
        }
    }
    __syncthreads();
    __half* rb = g_reconh + ((size_t)b * 64 + c) * HWSZ;
    for (int s = threadIdx.x; s < 512; s += 256) {
        int wlh = s & 63, hs = s >> 6;
        int hb = hs * 4, ib = hb >> 1;
        uint64_t acc01 = z2, acc23 = z2;
        #pragma unroll
        for (int k = 0; k < 4; k++) {
            const uint64_t* rr = (k & 1) ? qhi : qlo;
            uint64_t tp[5];
            #pragma unroll
            for (int m = 0; m < 5; m++) {
                float tv = stmp[k][ib + m][wlh];
                tp[m] = pk2(tv, tv);
            }
            #pragma unroll
            for (int m = 0; m < 4; m++) {
                acc01 = fma2(tp[m],     rr[m], acc01);
                acc23 = fma2(tp[m + 1], rr[m], acc23);
            }
        }
        float a0, a1, a2, a3;
        upk2(acc01, a0, a1); upk2(acc23, a2, a3);
        rb[(h0 + hb + 0) * WW + w0 + wlh] = __float2half(a0);
        rb[(h0 + hb + 1) * WW + w0 + wlh] = __float2half(a1);
        rb[(h0 + hb + 2) * WW + w0 + wlh] = __float2half(a2);
        rb[(h0 + hb + 3) * WW + w0 + wlh] = __float2half(a3);
    }
}

// ---------------- K7: fused = x @ wfx^T + bf + reconMixed (fp16 mma, K=64) ----------------
__global__ void __launch_bounds__(256) k_final(const float* __restrict__ x,
                                               const float* __restrict__ bf,
                                               float* __restrict__ out) {
    const int b = blockIdx.y;
    const int p0 = blockIdx.x * 256;
    __shared__ __half sW[2][64][24];
    __shared__ __half sA[2][16][264];
    const int tid = threadIdx.x;
    const int w = tid >> 5, lane = tid & 31;
    const int gid = lane >> 2, tig = lane & 3;
    const int obase = (w >> 2) * 32, pbase = (w & 3) * 64;
    float4 acc[2][8] = {};
    const float* xb = x + (size_t)b * 64 * HWSZ;
    const __half* rbh = g_reconh + (size_t)b * 64 * HWSZ;

    const int row0 = tid >> 5, cb0 = (tid & 31) * 8;
    const int wo0 = tid >> 1, wk8 = (tid & 1) * 8;
    uint4 ra[2]; uint4 rwv;

    #define G3_LOAD(cc) do { \
        _Pragma("unroll") \
        for (int s = 0; s < 2; s++) { \
            int ch = (cc) + row0 + s * 8; \
            const float* src = &xb[(size_t)ch * HWSZ + p0 + cb0]; \
            float4 v0 = *(const float4*)src; \
            float4 v1 = *(const float4*)(src + 4); \
            ra[s].x = packh2(v0.x, v0.y); ra[s].y = packh2(v0.z, v0.w); \
            ra[s].z = packh2(v1.x, v1.y); ra[s].w = packh2(v1.z, v1.w); \
        } \
        if (tid < 128) rwv = *(const uint4*)&g_wfh[wo0 * 128 + (cc) + wk8]; \
    } while (0)
    #define G3_STORE(st) do { \
        _Pragma("unroll") \
        for (int s = 0; s < 2; s++) \
            *(uint4*)&sA[st][row0 + s * 8][cb0] = ra[s]; \
        if (tid < 128) *(uint4*)&sW[st][wo0][wk8] = rwv; \
    } while (0)

    uint32_t saddrA = (uint32_t)__cvta_generic_to_shared(&sA[0][0][0]);
    uint32_t saddrW = (uint32_t)__cvta_generic_to_shared(&sW[0][0][0]);
    const int q = lane >> 3, r = lane & 7;
    const uint32_t aoff = (uint32_t)((((q & 1) * 8 + r) * 264 + (q >> 1) * 8) * 2);
    const uint32_t woff0 = (uint32_t)(((obase + (q & 1) * 8 + r) * 24 + (q >> 1) * 8) * 2);
    const uint32_t woff1 = woff0 + 16 * 24 * 2;

    G3_LOAD(0); G3_STORE(0);
    __syncthreads();
    int cur = 0;
    for (int cc = 0; cc < 64; cc += 16) {
        const bool hasnext = (cc + 16 < 64);
        if (hasnext) G3_LOAD(cc + 16);
        uint32_t baA = saddrA + (uint32_t)(cur * 16 * 264 * 2);
        uint32_t baW = saddrW + (uint32_t)(cur * 64 * 24 * 2);
        uint32_t wa0[4], wa1[4];
        ldsm4(wa0, baW + woff0);
        ldsm4(wa1, baW + woff1);
        #pragma unroll
        for (int j = 0; j < 4; j++) {
            uint32_t ab[4];
            ldsm4t(ab, baA + aoff + (uint32_t)((pbase + j * 16) * 2));
            mma_f16(acc[0][2 * j],     wa0, ab[0], ab[1]);
            mma_f16(acc[1][2 * j],     wa1, ab[0], ab[1]);
            mma_f16(acc[0][2 * j + 1], wa0, ab[2], ab[3]);
            mma_f16(acc[1][2 * j + 1], wa1, ab[2], ab[3]);
        }
        if (hasnext) G3_STORE(cur ^ 1);
        __syncthreads();
        cur ^= 1;
    }
    float* ob = out + (size_t)b * 64 * HWSZ;
    #pragma unroll
    for (int mt = 0; mt < 2; mt++) {
        int o1 = obase + mt * 16 + gid;
        float bia = bf[o1], bib = bf[o1 + 8];
        #pragma unroll
        for (int nt = 0; nt < 8; nt++) {
            int p = p0 + pbase + nt * 8 + 2 * tig;
            float2 r0 = __half22float2(*(const __half2*)&rbh[(size_t)o1 * HWSZ + p]);
            float2 r1 = __half22float2(*(const __half2*)&rbh[(size_t)(o1 + 8) * HWSZ + p]);
            *(float2*)&ob[(size_t)o1 * HWSZ + p] =
                make_float2(acc[mt][nt].x + bia + r0.x, acc[mt][nt].y + bia + r0.y);
            *(float2*)&ob[(size_t)(o1 + 8) * HWSZ + p] =
                make_float2(acc[mt][nt].z + bib + r1.x, acc[mt][nt].w + bib + r1.y);
        }
    }
}

extern "C" void kernel_launch(void* const* d_in, const int* in_sizes, int n_in,
                              void* d_out, int out_size) {
    const float* x     = (const float*)d_in[0];
    const float* w1    = (const float*)d_in[1];
    const float* b1    = (const float*)d_in[2];
    const float* gamma = (const float*)d_in[3];
    const float* beta  = (const float*)d_in[4];
    const float* w2    = (const float*)d_in[5];
    const float* b2    = (const float*)d_in[6];
    const float* g1    = (const float*)d_in[7];
    const float* gb1   = (const float*)d_in[8];
    const float* g2    = (const float*)d_in[9];
    const float* gb2   = (const float*)d_in[10];
    const float* wf    = (const float*)d_in[11];
    const float* bf    = (const float*)d_in[12];
    float* out = (float*)d_out;

    k_prep<<<128, 256>>>(w1, w2, wf, b2);
    k_dwt<<<dim3(17, 512), 256>>>(x);
    k_gemm1<<<dim3(135, 8), 256>>>(b1);
    k_gn<<<dim3(128, 8), 256>>>(gamma, beta, g1, gb1, g2, gb2);
    k_gemm2<<<dim3(135, 2, 8), 256>>>();
    k_idwt<<<dim3(32, 512), 256>>>();
    k_final<<<dim3(256, 8), 256>>>(x, bf, out);
}